// round 15
// baseline (speedup 1.0000x reference)
#include <cuda_runtime.h>
#include <cstdint>

// YOLO v1 loss: S=7, NB=2, C=20. predictions [N, 7*7*30], targets [N,7,7,25].
// R7 structure (measured best: TPB=256, one-shot warp-private cp.async staging,
// 4 CTAs/SM) + device-side scalar publish (no zero_out launch).

#define S_ 7
#define C_ 20
#define CELL_PRED 30   // C + NB*5
#define CELL_TGT  25   // C + 5
#define LAMBDA_COORD 5.0f
#define LAMBDA_NOOBJ 0.5f
#define EPS_ 1e-6f

#define TPB 256
#define WARPS (TPB / 32)
#define CELLS_PER_CTA (WARPS * 32)               // 256
#define WARP_PRED_F4 240                         // 32*30/4
#define WARP_TGT_F4  200                         // 32*25/4
#define WARP_SLICE_F (32 * (CELL_PRED + CELL_TGT))   // 1760 floats = 7040 B

__device__ float        g_partial;   // zero-initialized at module load
__device__ unsigned int g_count;

__device__ __forceinline__ void cp16(unsigned int smem_dst, const void* gmem_src) {
    asm volatile("cp.async.cg.shared.global [%0], [%1], 16;"
                 :: "r"(smem_dst), "l"(gmem_src));
}
__device__ __forceinline__ void cp_commit_wait() {
    asm volatile("cp.async.commit_group;");
    asm volatile("cp.async.wait_group 0;" ::: "memory");
}

__device__ __forceinline__ float iou_mid_f2(
    float2 xy_a, float2 wh_a, float2 xy_b, float2 wh_b)
{
    float ax1 = xy_a.x - wh_a.x * 0.5f, ay1 = xy_a.y - wh_a.y * 0.5f;
    float ax2 = xy_a.x + wh_a.x * 0.5f, ay2 = xy_a.y + wh_a.y * 0.5f;
    float bx1 = xy_b.x - wh_b.x * 0.5f, by1 = xy_b.y - wh_b.y * 0.5f;
    float bx2 = xy_b.x + wh_b.x * 0.5f, by2 = xy_b.y + wh_b.y * 0.5f;
    float iw = fmaxf(fminf(ax2, bx2) - fmaxf(ax1, bx1), 0.0f);
    float ih = fmaxf(fminf(ay2, by2) - fmaxf(ay1, by1), 0.0f);
    float inter  = iw * ih;
    float area_a = fabsf((ax2 - ax1) * (ay2 - ay1));
    float area_b = fabsf((bx2 - bx1) * (by2 - by1));
    return inter / (area_a + area_b - inter + EPS_);
}

__global__ __launch_bounds__(TPB) void yolo_loss_kernel(
    const float* __restrict__ pred,
    const float* __restrict__ tgt,
    float* __restrict__ out,
    int total_cells,
    float invN)
{
    __shared__ float smem[WARPS * WARP_SLICE_F];   // 56320 B -> 4 CTAs/SM
    __shared__ float warp_sums[WARPS];

    const int lane = threadIdx.x & 31;
    const int wid  = threadIdx.x >> 5;

    const int cell_base = blockIdx.x * CELLS_PER_CTA + wid * 32;

    float* wp = smem + wid * WARP_SLICE_F;           // [0:960) pred floats
    float* wt = wp + 32 * CELL_PRED;                 // [960:1760) tgt floats
    unsigned int wp_addr = (unsigned int)__cvta_generic_to_shared(wp);
    unsigned int wt_addr = (unsigned int)__cvta_generic_to_shared(wt);

    if (cell_base + 32 <= total_cells) {
        // Fast path: coalesced 16B cp.async, L1 bypass. Bases 16B-aligned
        // (cell_base % 32 == 0 -> cell_base*120 and *100 are multiples of 16).
        const float4* gp = reinterpret_cast<const float4*>(pred + (size_t)cell_base * CELL_PRED);
        #pragma unroll
        for (int i = 0; i < 8; i++) {
            int idx = lane + i * 32;
            if (idx < WARP_PRED_F4) cp16(wp_addr + idx * 16, gp + idx);
        }
        const float4* gt = reinterpret_cast<const float4*>(tgt + (size_t)cell_base * CELL_TGT);
        #pragma unroll
        for (int i = 0; i < 7; i++) {
            int idx = lane + i * 32;
            if (idx < WARP_TGT_F4) cp16(wt_addr + idx * 16, gt + idx);
        }
        cp_commit_wait();
    } else {
        // Tail path: guarded scalar staging.
        int cells_here = total_cells - cell_base;
        if (cells_here < 0) cells_here = 0;
        const float* gp = pred + (size_t)cell_base * CELL_PRED;
        for (int i = lane; i < cells_here * CELL_PRED; i += 32) wp[i] = __ldg(gp + i);
        const float* gt = tgt + (size_t)cell_base * CELL_TGT;
        for (int i = lane; i < cells_here * CELL_TGT; i += 32) wt[i] = __ldg(gt + i);
    }
    __syncwarp();

    float v = 0.0f;
    if (cell_base + lane < total_cells) {
        // pred row: 8B-aligned (lane*120B) -> float2 reads
        const float2* p2 = reinterpret_cast<const float2*>(wp + lane * CELL_PRED);
        const float*  t  = wt + lane * CELL_TGT;

        // class loss (c = 0..19 as 10 float2)
        float cls = 0.0f;
        #pragma unroll
        for (int c = 0; c < C_ / 2; c++) {
            float2 pv = p2[c];
            float d0 = pv.x - t[2 * c];
            float d1 = pv.y - t[2 * c + 1];
            cls = fmaf(d0, d0, fmaf(d1, d1, cls));
        }

        bool obj = (t[C_] == 1.0f);

        // b1: floats 20..24 -> p2[10]=(x,y), p2[11]=(w,h), p2[12].x=conf1
        // b2: floats 25..29 -> p2[12].y=x2, p2[13]=(y2,w2), p2[14]=(h2,conf2)
        float2 b1xy = p2[10], b1wh = p2[11], pc = p2[12];
        float2 b2a  = p2[13], b2b  = p2[14];
        float2 b2xy = make_float2(pc.y,  b2a.x);
        float2 b2wh = make_float2(b2a.y, b2b.x);
        float  c1 = pc.x, c2 = b2b.y;

        float2 txy = make_float2(t[C_ + 0], t[C_ + 1]);
        float2 twh = make_float2(t[C_ + 2], t[C_ + 3]);

        float i1 = iou_mid_f2(b1xy, b1wh, txy, twh);
        float i2 = iou_mid_f2(b2xy, b2wh, txy, twh);
        bool first = (i1 > i2);
        float2 rxy = first ? b1xy : b2xy;
        float2 rwh = first ? b1wh : b2wh;
        float  rc  = first ? c1   : c2;

        float dx = rxy.x - txy.x;
        float dy = rxy.y - txy.y;
        float xy = fmaf(dx, dx, dy * dy);
        float dw = sqrtf(rwh.x) - sqrtf(twh.x);
        float dh = sqrtf(rwh.y) - sqrtf(twh.y);
        float wh = fmaf(dw, dw, dh * dh);
        float coord = LAMBDA_COORD * (xy + wh);
        float dc = rc - t[C_ + 4];
        float conf = dc * dc;

        float noobj = LAMBDA_NOOBJ * fmaf(c1, c1, c2 * c2);

        v = obj ? (coord + conf + cls) : noobj;
        v *= invN;
    }

    // warp reduce
    #pragma unroll
    for (int off = 16; off > 0; off >>= 1)
        v += __shfl_down_sync(0xFFFFFFFFu, v, off);
    if (lane == 0) warp_sums[wid] = v;
    __syncthreads();

    if (threadIdx.x == 0) {
        float s = warp_sums[0];
        #pragma unroll
        for (int w = 1; w < WARPS; w++) s += warp_sums[w];

        atomicAdd(&g_partial, s);
        __threadfence();
        unsigned int done = atomicAdd(&g_count, 1u);
        if (done == gridDim.x - 1) {              // last CTA publishes + resets
            out[0] = g_partial;
            g_partial = 0.0f;
            g_count = 0u;
            __threadfence();
        }
    }
}

extern "C" void kernel_launch(void* const* d_in, const int* in_sizes, int n_in,
                              void* d_out, int out_size)
{
    const float* pred = (const float*)d_in[0];
    const float* tgt  = (const float*)d_in[1];
    float* out = (float*)d_out;

    int N = in_sizes[0] / (S_ * S_ * (C_ + 10));
    int total_cells = N * S_ * S_;
    float invN = 1.0f / (float)N;

    int blocks = (total_cells + CELLS_PER_CTA - 1) / CELLS_PER_CTA;
    yolo_loss_kernel<<<blocks, TPB>>>(pred, tgt, out, total_cells, invN);
}

// round 17
// speedup vs baseline: 1.0133x; 1.0133x over previous
#include <cuda_runtime.h>
#include <cstdint>

// YOLO v1 loss: S=7, NB=2, C=20. predictions [N, 7*7*30], targets [N,7,7,25].
// R7 structure (measured best: TPB=256, one-shot warp-private cp.async staging,
// 4 CTAs/SM, scalar body) + cheap release/acquire device-side publish
// (no zero_out launch, no __threadfence).

#define S_ 7
#define C_ 20
#define CELL_PRED 30   // C + NB*5
#define CELL_TGT  25   // C + 5
#define LAMBDA_COORD 5.0f
#define LAMBDA_NOOBJ 0.5f
#define EPS_ 1e-6f

#define TPB 256
#define WARPS (TPB / 32)
#define CELLS_PER_CTA (WARPS * 32)               // 256
#define WARP_PRED_F4 240                         // 32*30/4
#define WARP_TGT_F4  200                         // 32*25/4
#define WARP_SLICE_F (32 * (CELL_PRED + CELL_TGT))   // 1760 floats = 7040 B

__device__ float        g_partial;   // zero-initialized at module load
__device__ unsigned int g_count;

__device__ __forceinline__ void cp16(unsigned int smem_dst, const void* gmem_src) {
    asm volatile("cp.async.cg.shared.global [%0], [%1], 16;"
                 :: "r"(smem_dst), "l"(gmem_src));
}
__device__ __forceinline__ void cp_commit_wait() {
    asm volatile("cp.async.commit_group;");
    asm volatile("cp.async.wait_group 0;" ::: "memory");
}

__device__ __forceinline__ float iou_mid(const float* a, const float* b) {
    float ax1 = a[0] - a[2] * 0.5f, ay1 = a[1] - a[3] * 0.5f;
    float ax2 = a[0] + a[2] * 0.5f, ay2 = a[1] + a[3] * 0.5f;
    float bx1 = b[0] - b[2] * 0.5f, by1 = b[1] - b[3] * 0.5f;
    float bx2 = b[0] + b[2] * 0.5f, by2 = b[1] + b[3] * 0.5f;
    float iw = fmaxf(fminf(ax2, bx2) - fmaxf(ax1, bx1), 0.0f);
    float ih = fmaxf(fminf(ay2, by2) - fmaxf(ay1, by1), 0.0f);
    float inter  = iw * ih;
    float area_a = fabsf((ax2 - ax1) * (ay2 - ay1));
    float area_b = fabsf((bx2 - bx1) * (by2 - by1));
    return inter / (area_a + area_b - inter + EPS_);
}

__global__ __launch_bounds__(TPB) void yolo_loss_kernel(
    const float* __restrict__ pred,
    const float* __restrict__ tgt,
    float* __restrict__ out,
    int total_cells,
    float invN)
{
    __shared__ float smem[WARPS * WARP_SLICE_F];   // 56320 B -> 4 CTAs/SM
    __shared__ float warp_sums[WARPS];

    const int lane = threadIdx.x & 31;
    const int wid  = threadIdx.x >> 5;

    const int cell_base = blockIdx.x * CELLS_PER_CTA + wid * 32;

    float* wp = smem + wid * WARP_SLICE_F;           // [0:960) pred floats
    float* wt = wp + 32 * CELL_PRED;                 // [960:1760) tgt floats
    unsigned int wp_addr = (unsigned int)__cvta_generic_to_shared(wp);
    unsigned int wt_addr = (unsigned int)__cvta_generic_to_shared(wt);

    if (cell_base + 32 <= total_cells) {
        // Fast path: coalesced 16B cp.async, L1 bypass. Bases 16B-aligned
        // (cell_base % 32 == 0 -> cell_base*120 and *100 are multiples of 16).
        const float4* gp = reinterpret_cast<const float4*>(pred + (size_t)cell_base * CELL_PRED);
        #pragma unroll
        for (int i = 0; i < 8; i++) {
            int idx = lane + i * 32;
            if (idx < WARP_PRED_F4) cp16(wp_addr + idx * 16, gp + idx);
        }
        const float4* gt = reinterpret_cast<const float4*>(tgt + (size_t)cell_base * CELL_TGT);
        #pragma unroll
        for (int i = 0; i < 7; i++) {
            int idx = lane + i * 32;
            if (idx < WARP_TGT_F4) cp16(wt_addr + idx * 16, gt + idx);
        }
        cp_commit_wait();
    } else {
        // Tail path: guarded scalar staging.
        int cells_here = total_cells - cell_base;
        if (cells_here < 0) cells_here = 0;
        const float* gp = pred + (size_t)cell_base * CELL_PRED;
        for (int i = lane; i < cells_here * CELL_PRED; i += 32) wp[i] = __ldg(gp + i);
        const float* gt = tgt + (size_t)cell_base * CELL_TGT;
        for (int i = lane; i < cells_here * CELL_TGT; i += 32) wt[i] = __ldg(gt + i);
    }
    __syncwarp();

    float v = 0.0f;
    if (cell_base + lane < total_cells) {
        const float* p = wp + lane * CELL_PRED;
        const float* t = wt + lane * CELL_TGT;

        float cls = 0.0f;
        #pragma unroll
        for (int c = 0; c < C_; c++) {
            float d = p[c] - t[c];
            cls = fmaf(d, d, cls);
        }

        bool obj = (t[C_] == 1.0f);

        float i1 = iou_mid(p + C_,     t + C_);
        float i2 = iou_mid(p + C_ + 5, t + C_);
        const float* r = (i1 > i2) ? (p + C_) : (p + C_ + 5);

        float dx = r[0] - t[C_ + 0];
        float dy = r[1] - t[C_ + 1];
        float xy = fmaf(dx, dx, dy * dy);
        float dw = sqrtf(r[2]) - sqrtf(t[C_ + 2]);
        float dh = sqrtf(r[3]) - sqrtf(t[C_ + 3]);
        float wh = fmaf(dw, dw, dh * dh);
        float coord = LAMBDA_COORD * (xy + wh);
        float dc = r[4] - t[C_ + 4];
        float conf = dc * dc;

        float c1 = p[C_ + 4];
        float c2 = p[C_ + 9];
        float noobj = LAMBDA_NOOBJ * fmaf(c1, c1, c2 * c2);

        v = obj ? (coord + conf + cls) : noobj;
        v *= invN;
    }

    // warp reduce
    #pragma unroll
    for (int off = 16; off > 0; off >>= 1)
        v += __shfl_down_sync(0xFFFFFFFFu, v, off);
    if (lane == 0) warp_sums[wid] = v;
    __syncthreads();

    if (threadIdx.x == 0) {
        float s = warp_sums[0];
        #pragma unroll
        for (int w = 1; w < WARPS; w++) s += warp_sums[w];

        // Fire-and-forget relaxed reduction of this CTA's partial.
        asm volatile("red.relaxed.gpu.global.add.f32 [%0], %1;"
                     :: "l"(&g_partial), "f"(s) : "memory");
        // Release-increment completion counter: orders the red above before
        // the increment becomes visible (no full MEMBAR needed).
        unsigned int old;
        asm volatile("atom.release.gpu.global.add.u32 %0, [%1], %2;"
                     : "=r"(old) : "l"(&g_count), "r"(1u) : "memory");
        if (old == gridDim.x - 1) {               // last CTA publishes + resets
            float val;
            asm volatile("ld.acquire.gpu.global.f32 %0, [%1];"
                         : "=f"(val) : "l"(&g_partial) : "memory");
            out[0] = val;
            g_partial = 0.0f;
            g_count = 0u;
        }
    }
}

extern "C" void kernel_launch(void* const* d_in, const int* in_sizes, int n_in,
                              void* d_out, int out_size)
{
    const float* pred = (const float*)d_in[0];
    const float* tgt  = (const float*)d_in[1];
    float* out = (float*)d_out;

    int N = in_sizes[0] / (S_ * S_ * (C_ + 10));
    int total_cells = N * S_ * S_;
    float invN = 1.0f / (float)N;

    int blocks = (total_cells + CELLS_PER_CTA - 1) / CELLS_PER_CTA;
    yolo_loss_kernel<<<blocks, TPB>>>(pred, tgt, out, total_cells, invN);
}